// round 12
// baseline (speedup 1.0000x reference)
#include <cuda_runtime.h>
#include <cuda_bf16.h>
#include <stdint.h>

#define TSEQ 512
#define FUT  64
#define NCTA 128
#define NTHR 512
#define PITCH 72                       // smem row pitch (bf16 elems) for K-chunk 64
#define APLANE (64*PITCH)              // elems per A plane
#define WPLANE (128*PITCH)             // elems per W plane
#define BUFB   ((2*APLANE + 2*WPLANE)*2)   // 55296 bytes per stage buffer
#define SMEMB  (2*BUFB)                // 110592 bytes dynamic smem

// ---------------- persistent device scratch ----------------
__device__ uint16_t g_W0h[2048*512],  g_W0l[2048*512];    // w_hh0 hi/lo (permuted rows)
__device__ uint16_t g_P0h[2048*512],  g_P0l[2048*512];    // pw_hh0
__device__ uint16_t g_W1h[2048*1024], g_W1l[2048*1024];   // [w_ih1|w_hh1]
__device__ uint16_t g_P1h[2048*1024], g_P1l[2048*1024];   // [pw_ih1|pw_hh1]
__device__ uint16_t g_Sh[2][256*1024], g_Sl[2][256*1024]; // state hi/lo planes [b][h0|h1]
__device__ float    g_Cst[1024*256];                      // cell, unit-major [j][b]
__device__ float    g_B0p[2048], g_B1p[2048], g_BP0p[2048], g_BP1p[2048];
__device__ float    g_X0p[2048], g_XPp[2048];
__device__ float    g_HP[2][16*256];                      // head partials [buf][nt*256+b]
__device__ unsigned g_cnt = 0, g_gen = 0;

// ---------------- helpers ----------------
__device__ __forceinline__ uint32_t smem_u32(const void* p) {
    uint32_t a;
    asm("{ .reg .u64 t; cvta.to.shared.u64 t, %1; cvt.u32.u64 %0, t; }" : "=r"(a) : "l"(p));
    return a;
}
#define CP16(dst, src) \
    asm volatile("cp.async.cg.shared.global [%0], [%1], 16;" :: "r"(dst), "l"(src))
#define LDSM4(r, adr) \
    asm volatile("ldmatrix.sync.aligned.m8n8.x4.shared.b16 {%0,%1,%2,%3}, [%4];" \
        : "=r"((r)[0]), "=r"((r)[1]), "=r"((r)[2]), "=r"((r)[3]) : "r"(adr))
#define MMA(c, a, b0v, b1v) \
    asm volatile("mma.sync.aligned.m16n8k16.row.col.f32.bf16.bf16.f32 " \
        "{%0,%1,%2,%3},{%4,%5,%6,%7},{%8,%9},{%0,%1,%2,%3};" \
        : "+f"((c)[0]), "+f"((c)[1]), "+f"((c)[2]), "+f"((c)[3]) \
        : "r"((a)[0]), "r"((a)[1]), "r"((a)[2]), "r"((a)[3]), "r"(b0v), "r"(b1v))

__device__ __forceinline__ float sigm(float x)  { return __fdividef(1.f, 1.f + __expf(-x)); }
__device__ __forceinline__ float tanh_(float x) { return __fdividef(2.f, 1.f + __expf(-2.f * x)) - 1.f; }

__device__ __forceinline__ void grid_sync() {
    __syncthreads();
    if (threadIdx.x == 0) {
        __threadfence();
        const unsigned gen = atomicAdd(&g_gen, 0u);
        if (atomicAdd(&g_cnt, 1u) == gridDim.x - 1u) {
            atomicExch(&g_cnt, 0u);
            __threadfence();
            atomicAdd(&g_gen, 1u);
        } else {
            while (atomicAdd(&g_gen, 0u) == gen) { }
        }
        __threadfence();
    }
    __syncthreads();
}

// ---------------------------------------------------------------------------
// One fused step: D[64 batch x 128 rows] = S[64,K] @ W[128,K]^T (3-term bf16
// hi/lo mma.sync, fp32 accum) + bias + rank-1 x + LSTM pointwise; writes hi/lo
// state planes + optional head partials. 16 warps: warp tile 16(m) x 32(n),
// wm=w&3 (16-row m-frag), wn=w>>2 (32-col n-tile). Rows permuted
// R = nt*128 + unit*4 + gate.
// ---------------------------------------------------------------------------
__device__ __noinline__ void run_step(
    const uint16_t* __restrict__ Wh, const uint16_t* __restrict__ Wl, int K,
    const uint16_t* __restrict__ Shr, const uint16_t* __restrict__ Slr,
    const float* __restrict__ biasP, const float* __restrict__ xwP,
    const float* __restrict__ xp,                              // xv = xp[b*TSEQ]
    const float* __restrict__ hpIn, const float* __restrict__ xbias,  // xv = sum+bias
    float* __restrict__ outCol,
    float* __restrict__ cbase,
    uint16_t* __restrict__ Shw, uint16_t* __restrict__ Slw, int uoff,
    const float* __restrict__ headw, float* __restrict__ hpOut,
    char* sm)
{
    const int tid = threadIdx.x, l = tid & 31, w = tid >> 5;
    const int wm = w & 3, wn = w >> 2;
    const int mb = wm * 16, nb = wn * 32;
    const int rr = blockIdx.x & 63;
    const int b0 = (rr & 3) * 64, R0 = (rr >> 2) * 128;
    const uint32_t su = smem_u32(sm);

    float acc[4][4];
    #pragma unroll
    for (int j = 0; j < 4; j++)
        #pragma unroll
        for (int k = 0; k < 4; k++) acc[j][k] = 0.f;

    const int NC = K >> 6;
    auto stage = [&](int c) {
        const uint32_t sb = su + (c & 1) * BUFB;
        const int k0 = c << 6;
        #pragma unroll
        for (int it = 0; it < 2; it++) {                  // A: 64 rows x 2 planes
            const int idx = tid + it * NTHR;
            const int pl = idx >> 9, r = (idx >> 3) & 63, sg = idx & 7;
            const uint16_t* src = (pl ? Slr : Shr) + (size_t)(b0 + r) * 1024 + k0 + sg * 8;
            CP16(sb + (pl * APLANE + r * PITCH + sg * 8) * 2, src);
        }
        #pragma unroll
        for (int it = 0; it < 4; it++) {                  // W: 128 rows x 2 planes
            const int idx = tid + it * NTHR;
            const int pl = idx >> 10, r = (idx >> 3) & 127, sg = idx & 7;
            const uint16_t* src = (pl ? Wl : Wh) + (size_t)(R0 + r) * K + k0 + sg * 8;
            CP16(sb + (2 * APLANE + pl * WPLANE + r * PITCH + sg * 8) * 2, src);
        }
        asm volatile("cp.async.commit_group;");
    };

    __syncthreads();                                      // smem reuse guard
    stage(0);
    const int arow = (l & 15), acol = (l >> 4) << 3;
    const int brow = (l & 7) + ((l >> 4) << 3), bcol = ((l >> 3) & 1) << 3;

    for (int c = 0; c < NC; c++) {
        if (c + 1 < NC) { stage(c + 1); asm volatile("cp.async.wait_group 1;"); }
        else            { asm volatile("cp.async.wait_group 0;"); }
        __syncthreads();
        const uint32_t sb = su + (c & 1) * BUFB;
        #pragma unroll
        for (int ks = 0; ks < 4; ks++) {
            uint32_t Ah[4], Al[4], Bh[2][4], Bl[2][4];
            {
                const uint32_t ao = sb + ((mb + arow) * PITCH + ks * 16 + acol) * 2;
                LDSM4(Ah, ao);
                LDSM4(Al, ao + APLANE * 2);
            }
            #pragma unroll
            for (int ng = 0; ng < 2; ng++) {
                const uint32_t bo = sb + (2 * APLANE) * 2 +
                                    ((nb + ng * 16 + brow) * PITCH + ks * 16 + bcol) * 2;
                LDSM4(Bh[ng], bo);
                LDSM4(Bl[ng], bo + WPLANE * 2);
            }
            #pragma unroll
            for (int nf = 0; nf < 4; nf++) {
                const int ng = nf >> 1, s2 = (nf & 1) * 2;
                MMA(acc[nf], Ah, Bh[ng][s2], Bh[ng][s2 + 1]);
                MMA(acc[nf], Ah, Bl[ng][s2], Bl[ng][s2 + 1]);
                MMA(acc[nf], Al, Bh[ng][s2], Bh[ng][s2 + 1]);
            }
        }
        __syncthreads();
    }

    // ---- epilogue (scratch overlays stage buffer 0; all MMAs drained) ----
    uint16_t* bhi = (uint16_t*)sm;
    uint16_t* blo = bhi + 64 * 40;
    float* hp_s = (float*)(blo + 64 * 40);
    float* xv_s = hp_s + 256;
    const bool hasx = (xp != nullptr) || (hpIn != nullptr);
    if (tid < 64) {
        const int b = b0 + tid;
        if (xp) xv_s[tid] = xp[(size_t)b * TSEQ];
        else if (hpIn) {
            float s = xbias[0];
            #pragma unroll
            for (int k = 0; k < 16; k++) s += hpIn[k * 256 + b];
            xv_s[tid] = s;
            if (R0 == 0 && outCol) outCol[(size_t)b * FUT] = s;
        }
    }
    __syncthreads();

    float hacc[2] = {0.f, 0.f};
    #pragma unroll
    for (int nf = 0; nf < 4; nf++) {
        const float d0 = acc[nf][0], d1 = acc[nf][1];
        const float d2 = acc[nf][2], d3 = acc[nf][3];
        const float g0 = __shfl_xor_sync(0xffffffffu, d0, 1);
        const float g1 = __shfl_xor_sync(0xffffffffu, d1, 1);
        const float g2 = __shfl_xor_sync(0xffffffffu, d2, 1);
        const float g3 = __shfl_xor_sync(0xffffffffu, d3, 1);
        if (!(l & 1)) {     // even lane of pair owns full unit (i,f local; g,o from partner)
            const int jloc = (nb + nf * 8 + 2 * (l & 3)) >> 2;
            const int jg = (R0 >> 2) + jloc;
            const float4 b4 = *(const float4*)(biasP + R0 + 4 * jloc);
            float4 x4 = make_float4(0.f, 0.f, 0.f, 0.f);
            if (xwP) x4 = *(const float4*)(xwP + R0 + 4 * jloc);
            const int rl = mb + (l >> 2);
            #pragma unroll
            for (int h8 = 0; h8 < 2; h8++) {
                const int row = rl + h8 * 8;
                float vi = (h8 ? d2 : d0) + b4.x;
                float vf = (h8 ? d3 : d1) + b4.y;
                float vg = (h8 ? g2 : g0) + b4.z;
                float vo = (h8 ? g3 : g1) + b4.w;
                if (hasx) {
                    const float xv = xv_s[row];
                    vi += xv * x4.x; vf += xv * x4.y;
                    vg += xv * x4.z; vo += xv * x4.w;
                }
                float* cp = cbase + (size_t)jg * 256 + b0 + row;
                const float cn = sigm(vf) * (*cp) + sigm(vi) * tanh_(vg);
                *cp = cn;
                const float hn = sigm(vo) * tanh_(cn);
                if (headw) hacc[h8] += hn * headw[jg];
                const __nv_bfloat16 hb = __float2bfloat16(hn);
                const __nv_bfloat16 lb = __float2bfloat16(hn - __bfloat162float(hb));
                bhi[row * 40 + jloc] = *(const uint16_t*)&hb;
                blo[row * 40 + jloc] = *(const uint16_t*)&lb;
            }
        }
    }
    if (headw) {
        #pragma unroll
        for (int h8 = 0; h8 < 2; h8++) {
            const float v = hacc[h8] + __shfl_xor_sync(0xffffffffu, hacc[h8], 2);
            if ((l & 3) == 0) hp_s[wn * 64 + mb + (l >> 2) + h8 * 8] = v;
        }
    }
    __syncthreads();
    if (tid < 256) {   // coalesced state writeback (16B per thread per plane)
        const int row = tid >> 2, sg = tid & 3;
        const size_t db = (size_t)(b0 + row) * 1024 + uoff + (R0 >> 2) + sg * 8;
        *(uint4*)(Shw + db) = *(const uint4*)(bhi + row * 40 + sg * 8);
        *(uint4*)(Slw + db) = *(const uint4*)(blo + row * 40 + sg * 8);
    }
    if (headw && tid < 64) {
        const float s = hp_s[tid] + hp_s[64 + tid] + hp_s[128 + tid] + hp_s[192 + tid];
        hpOut[(R0 >> 7) * 256 + b0 + tid] = s;
    }
}

// ---------------- persistent kernel: one graph node ----------------
__global__ __launch_bounds__(NTHR, 1) void lstm_mma(
    const float* __restrict__ x,
    const float* __restrict__ w_ih0, const float* __restrict__ w_hh0,
    const float* __restrict__ b_ih0, const float* __restrict__ b_hh0,
    const float* __restrict__ w_ih1, const float* __restrict__ w_hh1,
    const float* __restrict__ b_ih1, const float* __restrict__ b_hh1,
    const float* __restrict__ fc_w,  const float* __restrict__ fc_b,
    const float* __restrict__ pw_ih0, const float* __restrict__ pw_hh0,
    const float* __restrict__ pb_ih0, const float* __restrict__ pb_hh0,
    const float* __restrict__ pw_ih1, const float* __restrict__ pw_hh1,
    const float* __restrict__ pb_ih1, const float* __restrict__ pb_hh1,
    const float* __restrict__ pfc_w,  const float* __restrict__ pfc_b,
    float* __restrict__ out)
{
    extern __shared__ __align__(16) char sm[];
    const int tid = threadIdx.x;
    const int gt = blockIdx.x * NTHR + tid, gn = NCTA * NTHR;

    // ---- init: zero states/cells; permuted hi/lo weights; permuted biases ----
    for (int i = gt; i < 256 * 1024; i += gn) {
        g_Sh[0][i] = 0; g_Sh[1][i] = 0; g_Sl[0][i] = 0; g_Sl[1][i] = 0;
        g_Cst[i] = 0.f;
    }
    for (int i = gt; i < 2048 * 512; i += gn) {
        const int R = i >> 9, k = i & 511;
        const int r = (R & 3) * 512 + (R >> 7) * 32 + ((R & 127) >> 2);
        float v = w_hh0[r * 512 + k];
        __nv_bfloat16 hb = __float2bfloat16(v);
        __nv_bfloat16 lb = __float2bfloat16(v - __bfloat162float(hb));
        g_W0h[i] = *(uint16_t*)&hb; g_W0l[i] = *(uint16_t*)&lb;
        v = pw_hh0[r * 512 + k];
        hb = __float2bfloat16(v); lb = __float2bfloat16(v - __bfloat162float(hb));
        g_P0h[i] = *(uint16_t*)&hb; g_P0l[i] = *(uint16_t*)&lb;
    }
    for (int i = gt; i < 2048 * 1024; i += gn) {
        const int R = i >> 10, k = i & 1023;
        const int r = (R & 3) * 512 + (R >> 7) * 32 + ((R & 127) >> 2);
        float v = (k < 512) ? w_ih1[r * 512 + k] : w_hh1[r * 512 + k - 512];
        __nv_bfloat16 hb = __float2bfloat16(v);
        __nv_bfloat16 lb = __float2bfloat16(v - __bfloat162float(hb));
        g_W1h[i] = *(uint16_t*)&hb; g_W1l[i] = *(uint16_t*)&lb;
        v = (k < 512) ? pw_ih1[r * 512 + k] : pw_hh1[r * 512 + k - 512];
        hb = __float2bfloat16(v); lb = __float2bfloat16(v - __bfloat162float(hb));
        g_P1h[i] = *(uint16_t*)&hb; g_P1l[i] = *(uint16_t*)&lb;
    }
    for (int i = gt; i < 2048; i += gn) {
        const int r = (i & 3) * 512 + (i >> 7) * 32 + ((i & 127) >> 2);
        g_B0p[i]  = b_ih0[r] + b_hh0[r];
        g_B1p[i]  = b_ih1[r] + b_hh1[r];
        g_BP0p[i] = pb_ih0[r] + pb_hh0[r];
        g_BP1p[i] = pb_ih1[r] + pb_hh1[r];
        g_X0p[i]  = w_ih0[r];
        g_XPp[i]  = pw_ih0[r];
    }
    grid_sync();

    const bool isL1 = (blockIdx.x < 64);

    // ---- phase 0: L0(0) (reads zero state) ----
    if (!isL1)
        run_step(g_W0h, g_W0l, 512, g_Sh[0], g_Sl[0], g_B0p, g_X0p, x,
                 nullptr, nullptr, nullptr, g_Cst, g_Sh[1], g_Sl[1], 0,
                 nullptr, nullptr, sm);
    grid_sync();

    // ---- warmup t=1..512: { L1(t-1) || L0(t) }, one barrier per phase ----
    for (int t = 1; t <= TSEQ; t++) {
        const int pi = t & 1, qi = 1 - pi;
        if (isL1)
            run_step(g_W1h, g_W1l, 1024, g_Sh[pi], g_Sl[pi], g_B1p, nullptr,
                     nullptr, nullptr, nullptr, nullptr,
                     g_Cst + 512 * 256, g_Sh[qi], g_Sl[qi], 512,
                     (t == TSEQ) ? fc_w : nullptr, g_HP[0], sm);
        else if (t < TSEQ)
            run_step(g_W0h, g_W0l, 512, g_Sh[pi], g_Sl[pi], g_B0p, g_X0p, x + t,
                     nullptr, nullptr, nullptr, g_Cst, g_Sh[qi], g_Sl[qi], 0,
                     nullptr, nullptr, sm);
        grid_sync();
    }

    // ---- decode s=1..63: phase A = pred L0(s) (+out col s-1); phase B = pred L1(s) ----
    for (int s = 1; s < FUT; s++) {
        const int ri = (s - 1) & 1, wi = s & 1;
        if (!isL1)
            run_step(g_P0h, g_P0l, 512, g_Sh[ri], g_Sl[ri], g_BP0p, g_XPp, nullptr,
                     g_HP[ri], (s == 1) ? fc_b : pfc_b, out + (s - 1),
                     g_Cst, g_Sh[wi], g_Sl[wi], 0, nullptr, nullptr, sm);
        grid_sync();
        if (isL1)
            run_step(g_P1h, g_P1l, 1024, g_Sh[wi], g_Sl[wi], g_BP1p, nullptr,
                     nullptr, nullptr, nullptr, nullptr,
                     g_Cst + 512 * 256, g_Sh[(s + 1) & 1], g_Sl[(s + 1) & 1], 512,
                     pfc_w, g_HP[wi], sm);
        grid_sync();
    }

    // ---- final out column 63 from HP[1] ----
    if (blockIdx.x == 0 && tid < 256) {
        float s = pfc_b[0];
        #pragma unroll
        for (int k = 0; k < 16; k++) s += g_HP[1][k * 256 + tid];
        out[(size_t)tid * FUT + 63] = s;
    }
}

// ---------------- host driver: one launch -> one graph node ----------------
extern "C" void kernel_launch(void* const* d_in, const int* in_sizes, int n_in,
                              void* d_out, int out_size) {
    (void)in_sizes; (void)n_in; (void)out_size;
    cudaFuncSetAttribute(lstm_mma, cudaFuncAttributeMaxDynamicSharedMemorySize, SMEMB);
    lstm_mma<<<NCTA, NTHR, SMEMB>>>(
        (const float*)d_in[0],
        (const float*)d_in[2],  (const float*)d_in[3],
        (const float*)d_in[4],  (const float*)d_in[5],
        (const float*)d_in[6],  (const float*)d_in[7],
        (const float*)d_in[8],  (const float*)d_in[9],
        (const float*)d_in[10], (const float*)d_in[11],
        (const float*)d_in[12], (const float*)d_in[13],
        (const float*)d_in[14], (const float*)d_in[15],
        (const float*)d_in[16], (const float*)d_in[17],
        (const float*)d_in[18], (const float*)d_in[19],
        (const float*)d_in[20], (const float*)d_in[21],
        (float*)d_out);
}

// round 13
// speedup vs baseline: 1.0862x; 1.0862x over previous
#include <cuda_runtime.h>
#include <cuda_bf16.h>
#include <stdint.h>

#define TSEQ 512
#define FUT  64
#define NCTA 128
#define NTHR 512
#define PITCH 72                       // smem row pitch (bf16 elems) for K-chunk 64
#define APLANE (64*PITCH)              // elems per A plane (M=64)
#define WPLANE (64*PITCH)              // elems per W plane (N=64)
#define BUFB   ((2*APLANE + 2*WPLANE)*2)   // 36864 bytes per stage buffer
#define SMEMB  (2*BUFB)                // 73728 bytes dynamic smem

// ---------------- persistent device scratch ----------------
__device__ uint16_t g_W0h[2048*512],  g_W0l[2048*512];    // w_hh0 hi/lo (permuted rows)
__device__ uint16_t g_P0h[2048*512],  g_P0l[2048*512];    // pw_hh0
__device__ uint16_t g_W1h[2048*1024], g_W1l[2048*1024];   // [w_ih1|w_hh1]
__device__ uint16_t g_P1h[2048*1024], g_P1l[2048*1024];   // [pw_ih1|pw_hh1]
__device__ uint16_t g_Sh[2][256*1024], g_Sl[2][256*1024]; // state hi/lo planes [b][h0|h1]
__device__ float    g_Cst[1024*256];                      // cell, unit-major [j][b]
__device__ float    g_B0p[2048], g_B1p[2048], g_BP0p[2048], g_BP1p[2048];
__device__ float    g_X0p[2048], g_XPp[2048];
__device__ float    g_HP[2][32*256];                      // head partials [buf][seg*256+b]
__device__ unsigned g_cnt = 0, g_gen = 0;

// ---------------- helpers ----------------
__device__ __forceinline__ uint32_t smem_u32(const void* p) {
    uint32_t a;
    asm("{ .reg .u64 t; cvta.to.shared.u64 t, %1; cvt.u32.u64 %0, t; }" : "=r"(a) : "l"(p));
    return a;
}
#define CP16(dst, src) \
    asm volatile("cp.async.cg.shared.global [%0], [%1], 16;" :: "r"(dst), "l"(src))
#define LDSM4(r, adr) \
    asm volatile("ldmatrix.sync.aligned.m8n8.x4.shared.b16 {%0,%1,%2,%3}, [%4];" \
        : "=r"((r)[0]), "=r"((r)[1]), "=r"((r)[2]), "=r"((r)[3]) : "r"(adr))
#define MMA(c, a, b0v, b1v) \
    asm volatile("mma.sync.aligned.m16n8k16.row.col.f32.bf16.bf16.f32 " \
        "{%0,%1,%2,%3},{%4,%5,%6,%7},{%8,%9},{%0,%1,%2,%3};" \
        : "+f"((c)[0]), "+f"((c)[1]), "+f"((c)[2]), "+f"((c)[3]) \
        : "r"((a)[0]), "r"((a)[1]), "r"((a)[2]), "r"((a)[3]), "r"(b0v), "r"(b1v))

__device__ __forceinline__ float sigm(float x)  { return __fdividef(1.f, 1.f + __expf(-x)); }
__device__ __forceinline__ float tanh_(float x) { return __fdividef(2.f, 1.f + __expf(-2.f * x)) - 1.f; }

__device__ __forceinline__ void grid_sync() {
    __syncthreads();
    if (threadIdx.x == 0) {
        __threadfence();
        const unsigned gen = atomicAdd(&g_gen, 0u);
        if (atomicAdd(&g_cnt, 1u) == gridDim.x - 1u) {
            atomicExch(&g_cnt, 0u);
            __threadfence();
            atomicAdd(&g_gen, 1u);
        } else {
            while (atomicAdd(&g_gen, 0u) == gen) { }
        }
        __threadfence();
    }
    __syncthreads();
}

// ---------------------------------------------------------------------------
// One fused tile step: D[64 batch x 64 rows] = S[64,K] @ W[64,K]^T (3-term
// bf16 hi/lo mma.sync, fp32 accum) + bias + rank-1 x + LSTM pointwise; writes
// hi/lo state planes + optional head partials. 16 warps: wm=w&3 (m16),
// wn=w>>2 (n16). Rows permuted R = seg*64 + unit*4 + gate. Tile given by
// (b0, R0) explicitly.
// ---------------------------------------------------------------------------
__device__ __noinline__ void run_step(
    const uint16_t* __restrict__ Wh, const uint16_t* __restrict__ Wl, int K,
    const uint16_t* __restrict__ Shr, const uint16_t* __restrict__ Slr,
    const float* __restrict__ biasP, const float* __restrict__ xwP,
    const float* __restrict__ xp,                              // xv = xp[b*TSEQ]
    const float* __restrict__ hpIn, const float* __restrict__ xbias,  // xv = sum+bias
    float* __restrict__ outCol,
    float* __restrict__ cbase,
    uint16_t* __restrict__ Shw, uint16_t* __restrict__ Slw, int uoff,
    const float* __restrict__ headw, float* __restrict__ hpOut,
    int b0, int R0,
    char* sm)
{
    const int tid = threadIdx.x, l = tid & 31, w = tid >> 5;
    const int wm = w & 3, wn = w >> 2;
    const int mb = wm * 16, nb = wn * 16;
    const uint32_t su = smem_u32(sm);

    float acc[2][4];
    #pragma unroll
    for (int j = 0; j < 2; j++)
        #pragma unroll
        for (int k = 0; k < 4; k++) acc[j][k] = 0.f;

    const int NC = K >> 6;
    auto stage = [&](int c) {
        const uint32_t sb = su + (c & 1) * BUFB;
        const int k0 = c << 6;
        #pragma unroll
        for (int it = 0; it < 2; it++) {                  // A: 64 rows x 2 planes
            const int idx = tid + it * NTHR;
            const int pl = idx >> 9, r = (idx >> 3) & 63, sg = idx & 7;
            const uint16_t* src = (pl ? Slr : Shr) + (size_t)(b0 + r) * 1024 + k0 + sg * 8;
            CP16(sb + (pl * APLANE + r * PITCH + sg * 8) * 2, src);
        }
        #pragma unroll
        for (int it = 0; it < 2; it++) {                  // W: 64 rows x 2 planes
            const int idx = tid + it * NTHR;
            const int pl = idx >> 9, r = (idx >> 3) & 63, sg = idx & 7;
            const uint16_t* src = (pl ? Wl : Wh) + (size_t)(R0 + r) * K + k0 + sg * 8;
            CP16(sb + (2 * APLANE + pl * WPLANE + r * PITCH + sg * 8) * 2, src);
        }
        asm volatile("cp.async.commit_group;");
    };

    __syncthreads();                                      // smem reuse guard
    stage(0);
    const int arow = (l & 15), acol = (l >> 4) << 3;
    const int brow = (l & 7) + ((l >> 4) << 3), bcol = ((l >> 3) & 1) << 3;

    for (int c = 0; c < NC; c++) {
        if (c + 1 < NC) { stage(c + 1); asm volatile("cp.async.wait_group 1;"); }
        else            { asm volatile("cp.async.wait_group 0;"); }
        __syncthreads();
        const uint32_t sb = su + (c & 1) * BUFB;
        #pragma unroll
        for (int ks = 0; ks < 4; ks++) {
            uint32_t Ah[4], Al[4], Bh[4], Bl[4];
            {
                const uint32_t ao = sb + ((mb + arow) * PITCH + ks * 16 + acol) * 2;
                LDSM4(Ah, ao);
                LDSM4(Al, ao + APLANE * 2);
            }
            {
                const uint32_t bo = sb + (2 * APLANE) * 2 +
                                    ((nb + brow) * PITCH + ks * 16 + bcol) * 2;
                LDSM4(Bh, bo);
                LDSM4(Bl, bo + WPLANE * 2);
            }
            #pragma unroll
            for (int nf = 0; nf < 2; nf++) {
                const int s2 = nf * 2;
                MMA(acc[nf], Ah, Bh[s2], Bh[s2 + 1]);
                MMA(acc[nf], Ah, Bl[s2], Bl[s2 + 1]);
                MMA(acc[nf], Al, Bh[s2], Bh[s2 + 1]);
            }
        }
        __syncthreads();
    }

    // ---- epilogue (scratch overlays stage buffer 0; all MMAs drained) ----
    uint16_t* bhi = (uint16_t*)sm;
    uint16_t* blo = bhi + 64 * 40;
    float* hp_s = (float*)(blo + 64 * 40);
    float* xv_s = hp_s + 256;
    const bool hasx = (xp != nullptr) || (hpIn != nullptr);
    if (tid < 64) {
        const int b = b0 + tid;
        if (xp) xv_s[tid] = xp[(size_t)b * TSEQ];
        else if (hpIn) {
            float s = xbias[0];
            #pragma unroll
            for (int k = 0; k < 32; k++) s += hpIn[k * 256 + b];
            xv_s[tid] = s;
            if (R0 == 0 && outCol) outCol[(size_t)b * FUT] = s;
        }
    }
    __syncthreads();

    float hacc[2] = {0.f, 0.f};
    #pragma unroll
    for (int nf = 0; nf < 2; nf++) {
        const float d0 = acc[nf][0], d1 = acc[nf][1];
        const float d2 = acc[nf][2], d3 = acc[nf][3];
        const float g0 = __shfl_xor_sync(0xffffffffu, d0, 1);
        const float g1 = __shfl_xor_sync(0xffffffffu, d1, 1);
        const float g2 = __shfl_xor_sync(0xffffffffu, d2, 1);
        const float g3 = __shfl_xor_sync(0xffffffffu, d3, 1);
        if (!(l & 1)) {     // even lane of pair owns full unit (i,f local; g,o from partner)
            const int jloc = (nb + nf * 8 + 2 * (l & 3)) >> 2;
            const int jg = (R0 >> 2) + jloc;
            const float4 b4 = *(const float4*)(biasP + R0 + 4 * jloc);
            float4 x4 = make_float4(0.f, 0.f, 0.f, 0.f);
            if (xwP) x4 = *(const float4*)(xwP + R0 + 4 * jloc);
            const int rl = mb + (l >> 2);
            #pragma unroll
            for (int h8 = 0; h8 < 2; h8++) {
                const int row = rl + h8 * 8;
                float vi = (h8 ? d2 : d0) + b4.x;
                float vf = (h8 ? d3 : d1) + b4.y;
                float vg = (h8 ? g2 : g0) + b4.z;
                float vo = (h8 ? g3 : g1) + b4.w;
                if (hasx) {
                    const float xv = xv_s[row];
                    vi += xv * x4.x; vf += xv * x4.y;
                    vg += xv * x4.z; vo += xv * x4.w;
                }
                float* cp = cbase + (size_t)jg * 256 + b0 + row;
                const float cn = sigm(vf) * (*cp) + sigm(vi) * tanh_(vg);
                *cp = cn;
                const float hn = sigm(vo) * tanh_(cn);
                if (headw) hacc[h8] += hn * headw[jg];
                const __nv_bfloat16 hb = __float2bfloat16(hn);
                const __nv_bfloat16 lb = __float2bfloat16(hn - __bfloat162float(hb));
                bhi[row * 40 + jloc] = *(const uint16_t*)&hb;
                blo[row * 40 + jloc] = *(const uint16_t*)&lb;
            }
        }
    }
    if (headw) {
        #pragma unroll
        for (int h8 = 0; h8 < 2; h8++) {
            const float v = hacc[h8] + __shfl_xor_sync(0xffffffffu, hacc[h8], 2);
            if ((l & 3) == 0) hp_s[wn * 64 + mb + (l >> 2) + h8 * 8] = v;
        }
    }
    __syncthreads();
    if (tid < 128) {   // coalesced state writeback: 64 rows x 16 units, hi+lo
        const int row = tid >> 1, sg = tid & 1;
        const size_t db = (size_t)(b0 + row) * 1024 + uoff + (R0 >> 2) + sg * 8;
        *(uint4*)(Shw + db) = *(const uint4*)(bhi + row * 40 + sg * 8);
        *(uint4*)(Slw + db) = *(const uint4*)(blo + row * 40 + sg * 8);
    }
    if (headw && tid < 64) {
        const float s = hp_s[tid] + hp_s[64 + tid] + hp_s[128 + tid] + hp_s[192 + tid];
        hpOut[(R0 >> 6) * 256 + b0 + tid] = s;
    }
}

// ---------------- persistent kernel: one graph node ----------------
__global__ __launch_bounds__(NTHR, 1) void lstm_mma(
    const float* __restrict__ x,
    const float* __restrict__ w_ih0, const float* __restrict__ w_hh0,
    const float* __restrict__ b_ih0, const float* __restrict__ b_hh0,
    const float* __restrict__ w_ih1, const float* __restrict__ w_hh1,
    const float* __restrict__ b_ih1, const float* __restrict__ b_hh1,
    const float* __restrict__ fc_w,  const float* __restrict__ fc_b,
    const float* __restrict__ pw_ih0, const float* __restrict__ pw_hh0,
    const float* __restrict__ pb_ih0, const float* __restrict__ pb_hh0,
    const float* __restrict__ pw_ih1, const float* __restrict__ pw_hh1,
    const float* __restrict__ pb_ih1, const float* __restrict__ pb_hh1,
    const float* __restrict__ pfc_w,  const float* __restrict__ pfc_b,
    float* __restrict__ out)
{
    extern __shared__ __align__(16) char sm[];
    const int tid = threadIdx.x;
    const int gt = blockIdx.x * NTHR + tid, gn = NCTA * NTHR;

    // ---- init: zero states/cells; permuted hi/lo weights; permuted biases ----
    // row permute: R = seg*64 + unit*4 + gate  <-  orig gate*512 + seg*16 + unit
    // (inverse used below: r(R) = (R&3)*512 + (R>>6)*16 + ((R&63)>>2))
    for (int i = gt; i < 256 * 1024; i += gn) {
        g_Sh[0][i] = 0; g_Sh[1][i] = 0; g_Sl[0][i] = 0; g_Sl[1][i] = 0;
        g_Cst[i] = 0.f;
    }
    for (int i = gt; i < 2048 * 512; i += gn) {
        const int R = i >> 9, k = i & 511;
        const int r = (R & 3) * 512 + (R >> 6) * 16 + ((R & 63) >> 2);
        float v = w_hh0[r * 512 + k];
        __nv_bfloat16 hb = __float2bfloat16(v);
        __nv_bfloat16 lb = __float2bfloat16(v - __bfloat162float(hb));
        g_W0h[i] = *(uint16_t*)&hb; g_W0l[i] = *(uint16_t*)&lb;
        v = pw_hh0[r * 512 + k];
        hb = __float2bfloat16(v); lb = __float2bfloat16(v - __bfloat162float(hb));
        g_P0h[i] = *(uint16_t*)&hb; g_P0l[i] = *(uint16_t*)&lb;
    }
    for (int i = gt; i < 2048 * 1024; i += gn) {
        const int R = i >> 10, k = i & 1023;
        const int r = (R & 3) * 512 + (R >> 6) * 16 + ((R & 63) >> 2);
        float v = (k < 512) ? w_ih1[r * 512 + k] : w_hh1[r * 512 + k - 512];
        __nv_bfloat16 hb = __float2bfloat16(v);
        __nv_bfloat16 lb = __float2bfloat16(v - __bfloat162float(hb));
        g_W1h[i] = *(uint16_t*)&hb; g_W1l[i] = *(uint16_t*)&lb;
        v = (k < 512) ? pw_ih1[r * 512 + k] : pw_hh1[r * 512 + k - 512];
        hb = __float2bfloat16(v); lb = __float2bfloat16(v - __bfloat162float(hb));
        g_P1h[i] = *(uint16_t*)&hb; g_P1l[i] = *(uint16_t*)&lb;
    }
    for (int i = gt; i < 2048; i += gn) {
        const int r = (i & 3) * 512 + (i >> 6) * 16 + ((i & 63) >> 2);
        g_B0p[i]  = b_ih0[r] + b_hh0[r];
        g_B1p[i]  = b_ih1[r] + b_hh1[r];
        g_BP0p[i] = pb_ih0[r] + pb_hh0[r];
        g_BP1p[i] = pb_ih1[r] + pb_hh1[r];
        g_X0p[i]  = w_ih0[r];
        g_XPp[i]  = pw_ih0[r];
    }
    grid_sync();

    // tile for this CTA: 4 batch-tiles (64) x 32 row-tiles (64)
    const int tt = blockIdx.x;
    const int tb0 = (tt & 3) * 64, tR0 = (tt >> 2) * 64;

    // ---- phase 0: L0(0) (reads zero state), all CTAs ----
    run_step(g_W0h, g_W0l, 512, g_Sh[0], g_Sl[0], g_B0p, g_X0p, x,
             nullptr, nullptr, nullptr, g_Cst, g_Sh[1], g_Sl[1], 0,
             nullptr, nullptr, tb0, tR0, sm);
    grid_sync();

    // ---- warmup t=1..512: every CTA does L1(t-1) tile then L0(t) tile ----
    for (int t = 1; t <= TSEQ; t++) {
        const int pi = t & 1, qi = 1 - pi;
        run_step(g_W1h, g_W1l, 1024, g_Sh[pi], g_Sl[pi], g_B1p, nullptr,
                 nullptr, nullptr, nullptr, nullptr,
                 g_Cst + 512 * 256, g_Sh[qi], g_Sl[qi], 512,
                 (t == TSEQ) ? fc_w : nullptr, g_HP[0], tb0, tR0, sm);
        if (t < TSEQ)
            run_step(g_W0h, g_W0l, 512, g_Sh[pi], g_Sl[pi], g_B0p, g_X0p, x + t,
                     nullptr, nullptr, nullptr, g_Cst, g_Sh[qi], g_Sl[qi], 0,
                     nullptr, nullptr, tb0, tR0, sm);
        grid_sync();
    }

    // ---- decode s=1..63: phase A = pred L0(s) (+out col s-1); phase B = pred L1(s) ----
    for (int s = 1; s < FUT; s++) {
        const int ri = (s - 1) & 1, wi = s & 1;
        run_step(g_P0h, g_P0l, 512, g_Sh[ri], g_Sl[ri], g_BP0p, g_XPp, nullptr,
                 g_HP[ri], (s == 1) ? fc_b : pfc_b, out + (s - 1),
                 g_Cst, g_Sh[wi], g_Sl[wi], 0, nullptr, nullptr, tb0, tR0, sm);
        grid_sync();
        run_step(g_P1h, g_P1l, 1024, g_Sh[wi], g_Sl[wi], g_BP1p, nullptr,
                 nullptr, nullptr, nullptr, nullptr,
                 g_Cst + 512 * 256, g_Sh[(s + 1) & 1], g_Sl[(s + 1) & 1], 512,
                 pfc_w, g_HP[wi], tb0, tR0, sm);
        grid_sync();
    }

    // ---- final out column 63 from HP[1] ----
    if (blockIdx.x == 0 && tid < 256) {
        float s = pfc_b[0];
        #pragma unroll
        for (int k = 0; k < 32; k++) s += g_HP[1][k * 256 + tid];
        out[(size_t)tid * FUT + 63] = s;
    }
}

// ---------------- host driver: one launch -> one graph node ----------------
extern "C" void kernel_launch(void* const* d_in, const int* in_sizes, int n_in,
                              void* d_out, int out_size) {
    (void)in_sizes; (void)n_in; (void)out_size;
    cudaFuncSetAttribute(lstm_mma, cudaFuncAttributeMaxDynamicSharedMemorySize, SMEMB);
    lstm_mma<<<NCTA, NTHR, SMEMB>>>(
        (const float*)d_in[0],
        (const float*)d_in[2],  (const float*)d_in[3],
        (const float*)d_in[4],  (const float*)d_in[5],
        (const float*)d_in[6],  (const float*)d_in[7],
        (const float*)d_in[8],  (const float*)d_in[9],
        (const float*)d_in[10], (const float*)d_in[11],
        (const float*)d_in[12], (const float*)d_in[13],
        (const float*)d_in[14], (const float*)d_in[15],
        (const float*)d_in[16], (const float*)d_in[17],
        (const float*)d_in[18], (const float*)d_in[19],
        (const float*)d_in[20], (const float*)d_in[21],
        (float*)d_out);
}

// round 17
// speedup vs baseline: 1.3721x; 1.2632x over previous
#include <cuda_runtime.h>
#include <cuda_fp16.h>
#include <stdint.h>

#define TSEQ 512
#define FUT  64
#define NCTA 128
#define NTHR 512
#define PITCH 72                       // smem row pitch (fp16 elems) for K-chunk 64
#define APLANE (64*PITCH)              // elems in A plane (single, fp16 state)
#define WPLANE (64*PITCH)              // elems per W plane (hi or lo)
#define BUFB   ((APLANE + 2*WPLANE)*2) // 27648 bytes per stage buffer
#define SMEMB  (2*BUFB)                // 55296 bytes dynamic smem

// ---------------- persistent device scratch ----------------
__device__ uint16_t g_W0h[2048*512],  g_W0l[2048*512];    // w_hh0 fp16 hi/lo (permuted rows)
__device__ uint16_t g_P0h[2048*512],  g_P0l[2048*512];    // pw_hh0
__device__ uint16_t g_W1h[2048*1024], g_W1l[2048*1024];   // [w_ih1|w_hh1]
__device__ uint16_t g_P1h[2048*1024], g_P1l[2048*1024];   // [pw_ih1|pw_hh1]
__device__ uint16_t g_Sf[2][256*1024];                    // fp16 state [b][h0|h1]
__device__ float    g_Cst[1024*256];                      // cell, unit-major [j][b]
__device__ float    g_B0p[2048], g_B1p[2048], g_BP0p[2048], g_BP1p[2048];
__device__ float    g_X0p[2048], g_XPp[2048];
__device__ float    g_HP[2][32*256];                      // head partials [buf][seg*256+b]
__device__ unsigned g_cnt = 0, g_gen = 0;

// ---------------- helpers ----------------
__device__ __forceinline__ uint32_t smem_u32(const void* p) {
    uint32_t a;
    asm("{ .reg .u64 t; cvta.to.shared.u64 t, %1; cvt.u32.u64 %0, t; }" : "=r"(a) : "l"(p));
    return a;
}
#define CP16(dst, src) \
    asm volatile("cp.async.cg.shared.global [%0], [%1], 16;" :: "r"(dst), "l"(src))
#define LDSM4(r, adr) \
    asm volatile("ldmatrix.sync.aligned.m8n8.x4.shared.b16 {%0,%1,%2,%3}, [%4];" \
        : "=r"((r)[0]), "=r"((r)[1]), "=r"((r)[2]), "=r"((r)[3]) : "r"(adr))
#define MMA(c, a, b0v, b1v) \
    asm volatile("mma.sync.aligned.m16n8k16.row.col.f32.f16.f16.f32 " \
        "{%0,%1,%2,%3},{%4,%5,%6,%7},{%8,%9},{%0,%1,%2,%3};" \
        : "+f"((c)[0]), "+f"((c)[1]), "+f"((c)[2]), "+f"((c)[3]) \
        : "r"((a)[0]), "r"((a)[1]), "r"((a)[2]), "r"((a)[3]), "r"(b0v), "r"(b1v))

__device__ __forceinline__ float sigm(float x)  { return __fdividef(1.f, 1.f + __expf(-x)); }
__device__ __forceinline__ float tanh_(float x) { return __fdividef(2.f, 1.f + __expf(-2.f * x)) - 1.f; }

// Grid barrier: atomic arrivals, PLAIN volatile-load polling (L2 broadcast,
// no atomic-ALU serialization) + nanosleep backoff.
__device__ __forceinline__ void grid_sync() {
    __syncthreads();
    if (threadIdx.x == 0) {
        __threadfence();
        const unsigned gen = *(volatile unsigned*)&g_gen;
        if (atomicAdd(&g_cnt, 1u) == gridDim.x - 1u) {
            atomicExch(&g_cnt, 0u);
            __threadfence();
            atomicAdd(&g_gen, 1u);
        } else {
            while (*(volatile unsigned*)&g_gen == gen) __nanosleep(64);
        }
        __threadfence();
    }
    __syncthreads();
}

// ---------------------------------------------------------------------------
// One fused tile step: D[64 batch x 64 rows] = S[64,K] @ W[64,K]^T with
// A = fp16 state (single plane), W = fp16 hi+lo (2 MMAs per fragment, fp32
// accum) + bias + rank-1 x + LSTM pointwise; writes fp16 state + optional
// head partials. 16 warps: wm=w&3 (m16), wn=w>>2 (n16). Rows permuted
// R = seg*64 + unit*4 + gate. Tile given by (b0, R0).
// ---------------------------------------------------------------------------
__device__ __noinline__ void run_step(
    const uint16_t* __restrict__ Wh, const uint16_t* __restrict__ Wl, int K,
    const uint16_t* __restrict__ Sr,
    const float* __restrict__ biasP, const float* __restrict__ xwP,
    const float* __restrict__ xp,                              // xv = xp[b*TSEQ]
    const float* __restrict__ hpIn, const float* __restrict__ xbias,  // xv = sum+bias
    float* __restrict__ outCol,
    float* __restrict__ cbase,
    uint16_t* __restrict__ Sw, int uoff,
    const float* __restrict__ headw, float* __restrict__ hpOut,
    int b0, int R0,
    char* sm)
{
    const int tid = threadIdx.x, l = tid & 31, w = tid >> 5;
    const int wm = w & 3, wn = w >> 2;
    const int mb = wm * 16, nb = wn * 16;
    const uint32_t su = smem_u32(sm);

    float acc[2][4];
    #pragma unroll
    for (int j = 0; j < 2; j++)
        #pragma unroll
        for (int k = 0; k < 4; k++) acc[j][k] = 0.f;

    const int NC = K >> 6;
    auto stage = [&](int c) {
        const uint32_t sb = su + (c & 1) * BUFB;
        const int k0 = c << 6;
        {                                                  // A: 64 rows, 1 plane
            const int r = tid >> 3, sg = tid & 7;
            const uint16_t* src = Sr + (size_t)(b0 + r) * 1024 + k0 + sg * 8;
            CP16(sb + (r * PITCH + sg * 8) * 2, src);
        }
        #pragma unroll
        for (int it = 0; it < 2; it++) {                   // W: 64 rows x 2 planes
            const int pl = it, r = (tid >> 3) & 63, sg = tid & 7;
            const uint16_t* src = (pl ? Wl : Wh) + (size_t)(R0 + r) * K + k0 + sg * 8;
            CP16(sb + (APLANE + pl * WPLANE + r * PITCH + sg * 8) * 2, src);
        }
        asm volatile("cp.async.commit_group;");
    };

    __syncthreads();                                      // smem reuse guard
    stage(0);
    const int arow = (l & 15), acol = (l >> 4) << 3;
    const int brow = (l & 7) + ((l >> 4) << 3), bcol = ((l >> 3) & 1) << 3;

    for (int c = 0; c < NC; c++) {
        if (c + 1 < NC) { stage(c + 1); asm volatile("cp.async.wait_group 1;"); }
        else            { asm volatile("cp.async.wait_group 0;"); }
        __syncthreads();
        const uint32_t sb = su + (c & 1) * BUFB;
        #pragma unroll
        for (int ks = 0; ks < 4; ks++) {
            uint32_t A[4], Bh[4], Bl[4];
            {
                const uint32_t ao = sb + ((mb + arow) * PITCH + ks * 16 + acol) * 2;
                LDSM4(A, ao);
            }
            {
                const uint32_t bo = sb + APLANE * 2 +
                                    ((nb + brow) * PITCH + ks * 16 + bcol) * 2;
                LDSM4(Bh, bo);
                LDSM4(Bl, bo + WPLANE * 2);
            }
            #pragma unroll
            for (int nf = 0; nf < 2; nf++) {
                const int s2 = nf * 2;
                MMA(acc[nf], A, Bh[s2], Bh[s2 + 1]);
                MMA(acc[nf], A, Bl[s2], Bl[s2 + 1]);
            }
        }
        __syncthreads();
    }

    // ---- epilogue (scratch overlays stage buffer 0; all MMAs drained) ----
    uint16_t* bhi = (uint16_t*)sm;
    float* hp_s = (float*)(bhi + 64 * 40);
    float* xv_s = hp_s + 256;
    const bool hasx = (xp != nullptr) || (hpIn != nullptr);
    if (tid < 64) {
        const int b = b0 + tid;
        if (xp) xv_s[tid] = xp[(size_t)b * TSEQ];
        else if (hpIn) {
            float s = xbias[0];
            #pragma unroll
            for (int k = 0; k < 32; k++) s += hpIn[k * 256 + b];
            xv_s[tid] = s;
            if (R0 == 0 && outCol) outCol[(size_t)b * FUT] = s;
        }
    }
    __syncthreads();

    float hacc[2] = {0.f, 0.f};
    #pragma unroll
    for (int nf = 0; nf < 2; nf++) {
        const float d0 = acc[nf][0], d1 = acc[nf][1];
        const float d2 = acc[nf][2], d3 = acc[nf][3];
        const float g0 = __shfl_xor_sync(0xffffffffu, d0, 1);
        const float g1 = __shfl_xor_sync(0xffffffffu, d1, 1);
        const float g2 = __shfl_xor_sync(0xffffffffu, d2, 1);
        const float g3 = __shfl_xor_sync(0xffffffffu, d3, 1);
        if (!(l & 1)) {     // even lane of pair owns full unit (i,f local; g,o from partner)
            const int jloc = (nb + nf * 8 + 2 * (l & 3)) >> 2;
            const int jg = (R0 >> 2) + jloc;
            const float4 b4 = *(const float4*)(biasP + R0 + 4 * jloc);
            float4 x4 = make_float4(0.f, 0.f, 0.f, 0.f);
            if (xwP) x4 = *(const float4*)(xwP + R0 + 4 * jloc);
            const int rl = mb + (l >> 2);
            #pragma unroll
            for (int h8 = 0; h8 < 2; h8++) {
                const int row = rl + h8 * 8;
                float vi = (h8 ? d2 : d0) + b4.x;
                float vf = (h8 ? d3 : d1) + b4.y;
                float vg = (h8 ? g2 : g0) + b4.z;
                float vo = (h8 ? g3 : g1) + b4.w;
                if (hasx) {
                    const float xv = xv_s[row];
                    vi += xv * x4.x; vf += xv * x4.y;
                    vg += xv * x4.z; vo += xv * x4.w;
                }
                float* cp = cbase + (size_t)jg * 256 + b0 + row;
                const float cn = sigm(vf) * (*cp) + sigm(vi) * tanh_(vg);
                *cp = cn;
                const float hn = sigm(vo) * tanh_(cn);
                if (headw) hacc[h8] += hn * headw[jg];
                const __half hh = __float2half_rn(hn);
                bhi[row * 40 + jloc] = *(const uint16_t*)&hh;
            }
        }
    }
    if (headw) {
        #pragma unroll
        for (int h8 = 0; h8 < 2; h8++) {
            const float v = hacc[h8] + __shfl_xor_sync(0xffffffffu, hacc[h8], 2);
            if ((l & 3) == 0) hp_s[wn * 64 + mb + (l >> 2) + h8 * 8] = v;
        }
    }
    __syncthreads();
    if (tid < 128) {   // coalesced state writeback: 64 rows x 16 units fp16
        const int row = tid >> 1, sg = tid & 1;
        const size_t db = (size_t)(b0 + row) * 1024 + uoff + (R0 >> 2) + sg * 8;
        *(uint4*)(Sw + db) = *(const uint4*)(bhi + row * 40 + sg * 8);
    }
    if (headw && tid < 64) {
        const float s = hp_s[tid] + hp_s[64 + tid] + hp_s[128 + tid] + hp_s[192 + tid];
        hpOut[(R0 >> 6) * 256 + b0 + tid] = s;
    }
}

// ---------------- persistent kernel: one graph node ----------------
__global__ __launch_bounds__(NTHR, 1) void lstm_mma(
    const float* __restrict__ x,
    const float* __restrict__ w_ih0, const float* __restrict__ w_hh0,
    const float* __restrict__ b_ih0, const float* __restrict__ b_hh0,
    const float* __restrict__ w_ih1, const float* __restrict__ w_hh1,
    const float* __restrict__ b_ih1, const float* __restrict__ b_hh1,
    const float* __restrict__ fc_w,  const float* __restrict__ fc_b,
    const float* __restrict__ pw_ih0, const float* __restrict__ pw_hh0,
    const float* __restrict__ pb_ih0, const float* __restrict__ pb_hh0,
    const float* __restrict__ pw_ih1, const float* __restrict__ pw_hh1,
    const float* __restrict__ pb_ih1, const float* __restrict__ pb_hh1,
    const float* __restrict__ pfc_w,  const float* __restrict__ pfc_b,
    float* __restrict__ out)
{
    extern __shared__ __align__(16) char sm[];
    const int tid = threadIdx.x;
    const int gt = blockIdx.x * NTHR + tid, gn = NCTA * NTHR;

    // ---- init: zero states/cells; permuted fp16 hi/lo weights; permuted biases ----
    // row permute: R = seg*64 + unit*4 + gate ; inverse r(R) = (R&3)*512 + (R>>6)*16 + ((R&63)>>2)
    for (int i = gt; i < 256 * 1024; i += gn) {
        g_Sf[0][i] = 0; g_Sf[1][i] = 0;
        g_Cst[i] = 0.f;
    }
    for (int i = gt; i < 2048 * 512; i += gn) {
        const int R = i >> 9, k = i & 511;
        const int r = (R & 3) * 512 + (R >> 6) * 16 + ((R & 63) >> 2);
        float v = w_hh0[r * 512 + k];
        __half hb = __float2half_rn(v);
        __half lb = __float2half_rn(v - __half2float(hb));
        g_W0h[i] = *(uint16_t*)&hb; g_W0l[i] = *(uint16_t*)&lb;
        v = pw_hh0[r * 512 + k];
        hb = __float2half_rn(v); lb = __float2half_rn(v - __half2float(hb));
        g_P0h[i] = *(uint16_t*)&hb; g_P0l[i] = *(uint16_t*)&lb;
    }
    for (int i = gt; i < 2048 * 1024; i += gn) {
        const int R = i >> 10, k = i & 1023;
        const int r = (R & 3) * 512 + (R >> 6) * 16 + ((R & 63) >> 2);
        float v = (k < 512) ? w_ih1[r * 512 + k] : w_hh1[r * 512 + k - 512];
        __half hb = __float2half_rn(v);
        __half lb = __float2half_rn(v - __half2float(hb));
        g_W1h[i] = *(uint16_t*)&hb; g_W1l[i] = *(uint16_t*)&lb;
        v = (k < 512) ? pw_ih1[r * 512 + k] : pw_hh1[r * 512 + k - 512];
        hb = __float2half_rn(v); lb = __float2half_rn(v - __half2float(hb));
        g_P1h[i] = *(uint16_t*)&hb; g_P1l[i] = *(uint16_t*)&lb;
    }
    for (int i = gt; i < 2048; i += gn) {
        const int r = (i & 3) * 512 + (i >> 6) * 16 + ((i & 63) >> 2);
        g_B0p[i]  = b_ih0[r] + b_hh0[r];
        g_B1p[i]  = b_ih1[r] + b_hh1[r];
        g_BP0p[i] = pb_ih0[r] + pb_hh0[r];
        g_BP1p[i] = pb_ih1[r] + pb_hh1[r];
        g_X0p[i]  = w_ih0[r];
        g_XPp[i]  = pw_ih0[r];
    }
    grid_sync();

    // tile for this CTA: 4 batch-tiles (64) x 32 row-tiles (64)
    const int tt = blockIdx.x;
    const int tb0 = (tt & 3) * 64, tR0 = (tt >> 2) * 64;

    // ---- phase 0: L0(0) (reads zero state), all CTAs ----
    run_step(g_W0h, g_W0l, 512, g_Sf[0], g_B0p, g_X0p, x,
             nullptr, nullptr, nullptr, g_Cst, g_Sf[1], 0,
             nullptr, nullptr, tb0, tR0, sm);
    grid_sync();

    // ---- warmup t=1..512: every CTA does L1(t-1) tile then L0(t) tile ----
    for (int t = 1; t <= TSEQ; t++) {
        const int pi = t & 1, qi = 1 - pi;
        run_step(g_W1h, g_W1l, 1024, g_Sf[pi], g_B1p, nullptr,
                 nullptr, nullptr, nullptr, nullptr,
                 g_Cst + 512 * 256, g_Sf[qi], 512,
                 (t == TSEQ) ? fc_w : nullptr, g_HP[0], tb0, tR0, sm);
        if (t < TSEQ)
            run_step(g_W0h, g_W0l, 512, g_Sf[pi], g_B0p, g_X0p, x + t,
                     nullptr, nullptr, nullptr, g_Cst, g_Sf[qi], 0,
                     nullptr, nullptr, tb0, tR0, sm);
        grid_sync();
    }

    // ---- decode s=1..63: phase A = pred L0(s) (+out col s-1); phase B = pred L1(s) ----
    for (int s = 1; s < FUT; s++) {
        const int ri = (s - 1) & 1, wi = s & 1;
        run_step(g_P0h, g_P0l, 512, g_Sf[ri], g_BP0p, g_XPp, nullptr,
                 g_HP[ri], (s == 1) ? fc_b : pfc_b, out + (s - 1),
                 g_Cst, g_Sf[wi], 0, nullptr, nullptr, tb0, tR0, sm);
        grid_sync();
        run_step(g_P1h, g_P1l, 1024, g_Sf[wi], g_BP1p, nullptr,
                 nullptr, nullptr, nullptr, nullptr,
                 g_Cst + 512 * 256, g_Sf[(s + 1) & 1], 512,
                 pfc_w, g_HP[wi], tb0, tR0, sm);
        grid_sync();
    }

    // ---- final out column 63 from HP[1] ----
    if (blockIdx.x == 0 && tid < 256) {
        float s = pfc_b[0];
        #pragma unroll
        for (int k = 0; k < 32; k++) s += g_HP[1][k * 256 + tid];
        out[(size_t)tid * FUT + 63] = s;
    }
}

// ---------------- host driver: one launch -> one graph node ----------------
extern "C" void kernel_launch(void* const* d_in, const int* in_sizes, int n_in,
                              void* d_out, int out_size) {
    (void)in_sizes; (void)n_in; (void)out_size;
    cudaFuncSetAttribute(lstm_mma, cudaFuncAttributeMaxDynamicSharedMemorySize, SMEMB);
    lstm_mma<<<NCTA, NTHR, SMEMB>>>(
        (const float*)d_in[0],
        (const float*)d_in[2],  (const float*)d_in[3],
        (const float*)d_in[4],  (const float*)d_in[5],
        (const float*)d_in[6],  (const float*)d_in[7],
        (const float*)d_in[8],  (const float*)d_in[9],
        (const float*)d_in[10], (const float*)d_in[11],
        (const float*)d_in[12], (const float*)d_in[13],
        (const float*)d_in[14], (const float*)d_in[15],
        (const float*)d_in[16], (const float*)d_in[17],
        (const float*)d_in[18], (const float*)d_in[19],
        (const float*)d_in[20], (const float*)d_in[21],
        (float*)d_out);
}